// round 1
// baseline (speedup 1.0000x reference)
#include <cuda_runtime.h>
#include <cstdint>
#include <cstddef>

// ---------------------------------------------------------------------------
// Problem constants (fixed by the dataset)
// ---------------------------------------------------------------------------
#define A_N   2000
#define P_N   20000
#define E_N   200000
#define MUL0  128
#define MUL1  64
#define DIM   320      // MUL0 + 3*MUL1
#define MID0  192      // MUL0 + MUL1
#define RDIM  768      // MID0 + 3*MID0  (scalar part 192 + vector part 576)

#define INV_SQRT10   0.31622776601683794f
#define INV_SQRT64   0.125f
#define INV_SQRT100  0.1f
#define INV_SQRT128  0.08838834764831845f
#define INV_SQRT192  0.07216878364870323f
#define INV_SQRT3    0.5773502691896258f

// ---------------------------------------------------------------------------
// Scratch (device globals -- no runtime allocation allowed)
// ---------------------------------------------------------------------------
__device__ __align__(16) float g_s0[A_N * MUL0];        // s0[a][u]         (u<128)
__device__ __align__(16) float g_s1[A_N * MID0];        // s1[a][v*3+m]     (v<64)
__device__ __align__(16) float g_r[(size_t)P_N * RDIM]; // segment-sum accumulator (61.4 MB)

// ---------------------------------------------------------------------------
// PTX helpers: packed fp32x2 FMA + vectorized global reduction
// ---------------------------------------------------------------------------
__device__ __forceinline__ void fma2(unsigned long long& d, unsigned long long a,
                                     unsigned long long b, unsigned long long c) {
    asm("fma.rn.f32x2 %0, %1, %2, %3;" : "=l"(d) : "l"(a), "l"(b), "l"(c));
}
__device__ __forceinline__ float2 unpack2(unsigned long long v) {
    float2 r;
    asm("mov.b64 {%0, %1}, %2;" : "=f"(r.x), "=f"(r.y) : "l"(v));
    return r;
}
__device__ __forceinline__ void red4(float* p, float a, float b, float c, float d) {
    asm volatile("red.global.add.v4.f32 [%0], {%1, %2, %3, %4};"
                 :: "l"(p), "f"(a), "f"(b), "f"(c), "f"(d) : "memory");
}

// ---------------------------------------------------------------------------
// K0: zero the accumulator
// ---------------------------------------------------------------------------
__global__ void zero_r_kernel() {
    size_t n = (size_t)P_N * RDIM / 4;
    float4* p = reinterpret_cast<float4*>(g_r);
    float4 z = make_float4(0.f, 0.f, 0.f, 0.f);
    for (size_t i = (size_t)blockIdx.x * blockDim.x + threadIdx.x; i < n;
         i += (size_t)gridDim.x * blockDim.x)
        p[i] = z;
}

// ---------------------------------------------------------------------------
// K1: sender transform  s0 = (x*attr)[:, :128] @ lin1_w0 / sqrt(128)
//                       s1[a,v,m] = sum_u x[a,128+u*3+m] * lin1_w1[u,v] / sqrt(64)
// one block per sender row, 192 threads
// ---------------------------------------------------------------------------
__global__ __launch_bounds__(192) void sender_kernel(
    const float* __restrict__ sin_, const float* __restrict__ sattr,
    const float* __restrict__ w0,   const float* __restrict__ w1) {
    __shared__ float xs[DIM];
    int a = blockIdx.x, tid = threadIdx.x;
    float at = sattr[a];
    for (int idx = tid; idx < DIM; idx += 192)
        xs[idx] = sin_[(size_t)a * DIM + idx] * at;
    __syncthreads();
    if (tid < MUL0) {
        float acc = 0.f;
        #pragma unroll 8
        for (int u = 0; u < MUL0; u++) acc += xs[u] * w0[u * MUL0 + tid];
        g_s0[a * MUL0 + tid] = acc * INV_SQRT128;
    }
    {
        int o = tid;                 // o < 192 always
        int v = o / 3, m = o - v * 3;
        float acc = 0.f;
        #pragma unroll 8
        for (int u = 0; u < MUL1; u++) acc += xs[MUL0 + u * 3 + m] * w1[u * MUL1 + v];
        g_s1[a * MID0 + o] = acc * INV_SQRT64;
    }
}

// ---------------------------------------------------------------------------
// K2: fused edge kernel.
//   phase A: h = silu(edge_scalars @ fc_w1 / sqrt(10))           -> smem (dup pairs)
//   phase B: weight = h @ fc_w2 / sqrt(100)  via FFMA2 register GEMM
//   phase C: gather g0/g1, form edge features, red.v4 into g_r
// 384 threads: tx = tid%96 owns weight columns [4*tx, 4*tx+4);
//              ty = tid/96, edges t = ty + 4*tt, tt<8  (32 edges/block)
// ---------------------------------------------------------------------------
__global__ __launch_bounds__(384) void edge_kernel(
    const int*   __restrict__ esrc,  const int*   __restrict__ edst,
    const float* __restrict__ eattr, const float* __restrict__ escal,
    const float* __restrict__ fw1,   const float* __restrict__ fw2) {
    __shared__ float  s_scal[32 * 10];
    __shared__ float2 s_h[32 * 100];     // (h, h) duplicated pairs for f32x2
    __shared__ int    s_src[32], s_dst[32];
    __shared__ float  s_att[32 * 4];

    int tid = threadIdx.x;
    int e0  = blockIdx.x * 32;

    if (tid < 32)       s_src[tid]      = esrc[e0 + tid];
    else if (tid < 64)  s_dst[tid - 32] = edst[e0 + tid - 32];
    if (tid < 128)      s_att[tid]      = eattr[e0 * 4 + tid];
    if (tid < 320)      s_scal[tid]     = escal[e0 * 10 + tid];
    __syncthreads();

    // phase A: 32 x 100 hidden activations
    for (int idx = tid; idx < 3200; idx += 384) {
        int t = idx / 100, k = idx - t * 100;
        float acc = 0.f;
        #pragma unroll
        for (int b = 0; b < 10; b++) acc += s_scal[t * 10 + b] * fw1[b * 100 + k];
        acc *= INV_SQRT10;
        float h = acc / (1.f + __expf(-acc));   // silu
        s_h[t * 100 + k] = make_float2(h, h);
    }
    __syncthreads();

    int tx = tid % 96, ty = tid / 96;
    const ulonglong2* W2 = reinterpret_cast<const ulonglong2*>(fw2);
    const unsigned long long* H = reinterpret_cast<const unsigned long long*>(s_h);

    unsigned long long acc[8][2];
    #pragma unroll
    for (int i = 0; i < 8; i++) { acc[i][0] = 0ull; acc[i][1] = 0ull; }

    // phase B: weight[t][4*tx .. 4*tx+3] for 8 edges, packed-pair FMAs
    #pragma unroll 4
    for (int k = 0; k < 100; k++) {
        ulonglong2 w = W2[k * 96 + tx];          // LDG.128: 4 consecutive W2 cols
        #pragma unroll
        for (int tt = 0; tt < 8; tt++) {
            unsigned long long hv = H[(ty + 4 * tt) * 100 + k];   // broadcast LDS.64
            fma2(acc[tt][0], hv, w.x, acc[tt][0]);
            fma2(acc[tt][1], hv, w.y, acc[tt][1]);
        }
    }

    // phase C: unpack, gather, scatter-reduce
    #pragma unroll
    for (int tt = 0; tt < 8; tt++) {
        int t = ty + 4 * tt;
        int s = s_src[t];
        size_t p = (size_t)s_dst[t];
        float sh0 = s_att[t * 4 + 0];
        float sx  = s_att[t * 4 + 1], sy = s_att[t * 4 + 2], sz = s_att[t * 4 + 3];
        float2 lo = unpack2(acc[tt][0]), hi = unpack2(acc[tt][1]);
        float q0 = lo.x * INV_SQRT100, q1 = lo.y * INV_SQRT100;
        float q2 = hi.x * INV_SQRT100, q3 = hi.y * INV_SQRT100;
        float* base = g_r + p * RDIM;

        if (tx < 32) {
            // w0 region: out0a[u] = w*g0[u]*sh0 -> r[p][u], u0 = 4*tx
            const float4 g = *reinterpret_cast<const float4*>(&g_s0[s * MUL0 + 4 * tx]);
            red4(base + 4 * tx, q0 * g.x * sh0, q1 * g.y * sh0,
                                q2 * g.z * sh0, q3 * g.w * sh0);
        } else if (tx < 64) {
            // w1 region: out1a[u][m] = w*g0[u]*sh1[m] -> r[p][192 + u*3 + m]
            int u0 = 4 * (tx - 32);
            const float4 g = *reinterpret_cast<const float4*>(&g_s0[s * MUL0 + u0]);
            float a0 = q0 * g.x, a1 = q1 * g.y, a2 = q2 * g.z, a3 = q3 * g.w;
            float* b = base + MID0 + 3 * u0;
            red4(b,     a0 * sx, a0 * sy, a0 * sz, a1 * sx);
            red4(b + 4, a1 * sy, a1 * sz, a2 * sx, a2 * sy);
            red4(b + 8, a2 * sz, a3 * sx, a3 * sy, a3 * sz);
        } else if (tx < 80) {
            // w2 region: out1b[v][m] = w*g1[v][m]*sh0 -> r[p][576 + v*3 + m]
            int v0 = 4 * (tx - 64);
            const float4* gp = reinterpret_cast<const float4*>(&g_s1[s * MID0 + 3 * v0]);
            float4 gA = gp[0], gB = gp[1], gC = gp[2];
            float* b = base + 576 + 3 * v0;
            red4(b,     q0 * gA.x * sh0, q0 * gA.y * sh0, q0 * gA.z * sh0, q1 * gA.w * sh0);
            red4(b + 4, q1 * gB.x * sh0, q1 * gB.y * sh0, q2 * gB.z * sh0, q2 * gB.w * sh0);
            red4(b + 8, q2 * gC.x * sh0, q3 * gC.y * sh0, q3 * gC.z * sh0, q3 * gC.w * sh0);
        } else {
            // w3 region: out0b[v] = w*dot(g1[v],sh1)/sqrt(3) -> r[p][128 + v]
            int v0 = 4 * (tx - 80);
            const float4* gp = reinterpret_cast<const float4*>(&g_s1[s * MID0 + 3 * v0]);
            float4 gA = gp[0], gB = gp[1], gC = gp[2];
            float d0 = gA.x * sx + gA.y * sy + gA.z * sz;
            float d1 = gA.w * sx + gB.x * sy + gB.y * sz;
            float d2 = gB.z * sx + gB.w * sy + gC.x * sz;
            float d3 = gC.y * sx + gC.z * sy + gC.w * sz;
            red4(base + MUL0 + v0, q0 * d0 * INV_SQRT3, q1 * d1 * INV_SQRT3,
                                   q2 * d2 * INV_SQRT3, q3 * d3 * INV_SQRT3);
        }
    }
}

// ---------------------------------------------------------------------------
// K3: receiver kernel -- sc path, conv path, angle, combine.
// 8 receiver rows per block, 320 threads (one output column each)
// ---------------------------------------------------------------------------
__global__ __launch_bounds__(320) void recv_kernel(
    const float* __restrict__ rin,  const float* __restrict__ rattr,
    const float* __restrict__ scw0, const float* __restrict__ scw1,
    const float* __restrict__ l2w0, const float* __restrict__ l2w1,
    const float* __restrict__ l3w,  float* __restrict__ out) {
    __shared__ float r_s[8][RDIM];
    __shared__ float x_s[8][DIM];
    __shared__ float ang[8];
    __shared__ float att_s[8];

    int tid = threadIdx.x;
    int p0  = blockIdx.x * 8;

    if (tid < 8) att_s[tid] = rattr[p0 + tid];
    __syncthreads();

    for (int idx = tid; idx < 8 * RDIM; idx += 320) {
        int i = idx / RDIM, c = idx - i * RDIM;
        r_s[i][c] = g_r[(size_t)(p0 + i) * RDIM + c] * (INV_SQRT10 * att_s[i]);
    }
    for (int idx = tid; idx < 8 * DIM; idx += 320) {
        int i = idx / DIM, c = idx - i * DIM;
        x_s[i][c] = rin[(size_t)(p0 + i) * DIM + c] * att_s[i];
    }
    __syncthreads();

    // angle[i] = 0.1 * (r0 . lin3) / sqrt(192), one warp per row
    {
        int w = tid / 32, l = tid % 32;
        if (w < 8) {
            float s = 0.f;
            #pragma unroll
            for (int c = l; c < MID0; c += 32) s += r_s[w][c] * l3w[c];
            #pragma unroll
            for (int o = 16; o > 0; o >>= 1) s += __shfl_xor_sync(0xffffffffu, s, o);
            if (l == 0) ang[w] = 0.1f * INV_SQRT192 * s;
        }
    }
    __syncthreads();

    int j = tid;
    float accS[8], accC[8];
    #pragma unroll
    for (int i = 0; i < 8; i++) { accS[i] = 0.f; accC[i] = 0.f; }

    if (j < MUL0) {
        // scalar outputs: sc0 and conv0
        for (int k = 0; k < MUL0; k++) {
            float wv = scw0[k * MUL0 + j];
            #pragma unroll
            for (int i = 0; i < 8; i++) accS[i] += x_s[i][k] * wv;
        }
        for (int c = 0; c < MID0; c++) {
            float wv = l2w0[c * MUL0 + j];
            #pragma unroll
            for (int i = 0; i < 8; i++) accC[i] += r_s[i][c] * wv;
        }
        #pragma unroll
        for (int i = 0; i < 8; i++) {
            float a = ang[i];
            out[(size_t)(p0 + i) * DIM + j] =
                __cosf(a) * (accS[i] * INV_SQRT128) + __sinf(a) * (accC[i] * INV_SQRT192);
        }
    } else {
        // vector outputs: sc1 and conv1, column j = 128 + v*3 + m
        int o = j - MUL0, v = o / 3, m = o - v * 3;
        for (int u = 0; u < MUL1; u++) {
            float wv = scw1[u * MUL1 + v];
            #pragma unroll
            for (int i = 0; i < 8; i++) accS[i] += x_s[i][MUL0 + u * 3 + m] * wv;
        }
        for (int c = 0; c < MID0; c++) {
            float wv = l2w1[c * MUL1 + v];
            #pragma unroll
            for (int i = 0; i < 8; i++) accC[i] += r_s[i][MID0 + c * 3 + m] * wv;
        }
        #pragma unroll
        for (int i = 0; i < 8; i++) {
            float a = ang[i];
            out[(size_t)(p0 + i) * DIM + j] =
                __cosf(a) * (accS[i] * INV_SQRT64) + __sinf(a) * (accC[i] * INV_SQRT192);
        }
    }
}

// ---------------------------------------------------------------------------
// launch
// ---------------------------------------------------------------------------
extern "C" void kernel_launch(void* const* d_in, const int* in_sizes, int n_in,
                              void* d_out, int out_size) {
    const float* sender_input   = (const float*)d_in[0];
    const float* sender_attr    = (const float*)d_in[1];
    const float* receiver_input = (const float*)d_in[2];
    const float* receiver_attr  = (const float*)d_in[3];
    const int*   edge_src       = (const int*)d_in[4];
    const int*   edge_dst       = (const int*)d_in[5];
    const float* edge_attr      = (const float*)d_in[6];
    const float* edge_scalars   = (const float*)d_in[7];
    const float* fc_w1          = (const float*)d_in[8];
    const float* fc_w2          = (const float*)d_in[9];
    const float* lin1_w0        = (const float*)d_in[10];
    const float* lin1_w1        = (const float*)d_in[11];
    const float* sc_w0          = (const float*)d_in[12];
    const float* sc_w1          = (const float*)d_in[13];
    const float* lin2_w0        = (const float*)d_in[14];
    const float* lin2_w1        = (const float*)d_in[15];
    const float* lin3_w         = (const float*)d_in[16];
    float* out = (float*)d_out;

    zero_r_kernel<<<2048, 256>>>();
    sender_kernel<<<A_N, 192>>>(sender_input, sender_attr, lin1_w0, lin1_w1);
    edge_kernel<<<E_N / 32, 384>>>(edge_src, edge_dst, edge_attr, edge_scalars,
                                   fc_w1, fc_w2);
    recv_kernel<<<P_N / 8, 320>>>(receiver_input, receiver_attr, sc_w0, sc_w1,
                                  lin2_w0, lin2_w1, lin3_w, out);
}